// round 13
// baseline (speedup 1.0000x reference)
#include <cuda_runtime.h>
#include <cstdint>

// ---------------------------------------------------------------------------
// y = W8(...(W0 x + b0)...) + b8  ->  y = W_eff x + b_eff,  W_eff [10,784].
// R13: gemv with WARP-PRIVATE cp.async (LDGSTS.cg) 4-stage pipeline:
//      MLP decoupled from registers -> DRAM-bound by construction.
//      No block barriers in the mainloop; per-warp commit/wait groups.
// ---------------------------------------------------------------------------

#define K_IN   784
#define N_OUT  10
#define DEPTH  4          // pipeline stages per warp
#define STGF   512        // floats per stage: 16 rows x 32 cols

__device__ float g_Weff[N_OUT * K_IN];
__device__ float g_beff[N_OUT];

// ---------------------------------------------------------------------------
// fold_fused: 7 CTAs x 768 threads (unchanged, known-correct).
// ---------------------------------------------------------------------------
template<int N, int M>
__device__ __forceinline__ void fold_step(float* A, float* T, float* beff,
    const float* W, const float* b, int t)
{
    if (t < N_OUT) {
        float s = 0.f;
#pragma unroll
        for (int k = 0; k < N; ++k) s += A[t * N + k] * b[k];
        beff[t] += s;
    }
    for (int idx = t; idx < N_OUT * M; idx += 768) {
        int r = idx / M, c = idx - r * M;
        float s = 0.f;
#pragma unroll
        for (int k = 0; k < N; ++k) s += A[r * N + k] * W[k * M + c];
        T[idx] = s;
    }
    __syncthreads();
    for (int idx = t; idx < N_OUT * M; idx += 768) A[idx] = T[idx];
    __syncthreads();
}

__global__ __launch_bounds__(768) void fold_fused(
    const float* __restrict__ W0, const float* __restrict__ b0,
    const float* __restrict__ W1, const float* __restrict__ b1,
    const float* __restrict__ W2, const float* __restrict__ b2,
    const float* __restrict__ W3, const float* __restrict__ b3,
    const float* __restrict__ W4, const float* __restrict__ b4,
    const float* __restrict__ W5, const float* __restrict__ b5,
    const float* __restrict__ W6, const float* __restrict__ b6,
    const float* __restrict__ W7, const float* __restrict__ b7,
    const float* __restrict__ W8, const float* __restrict__ b8)
{
    __shared__ float A[10 * 69], T[10 * 69], beff[N_OUT];
    __shared__ float sw[3049];
    __shared__ float sbv[170];

    const int t = threadIdx.x;

    float* sW1 = sw;          float* sW2 = sw + 2139;
    float* sW3 = sw + 2449;   float* sW4 = sw + 2549;
    float* sW5 = sw + 2649;   float* sW6 = sw + 2749;
    float* sW7 = sw + 2849;   float* sW8 = sw + 2949;
    float* sb0 = sbv;         float* sb1 = sbv + 69;
    float* sb2 = sbv + 100;   float* sb3 = sbv + 110;
    float* sb4 = sbv + 120;   float* sb5 = sbv + 130;
    float* sb6 = sbv + 140;   float* sb7 = sbv + 150;
    float* sb8 = sbv + 160;

    for (int i = t; i < 2139; i += 768) sW1[i] = W1[i];
    if (t < 310) sW2[t] = W2[t];
    if (t < 100) { sW3[t] = W3[t]; sW4[t] = W4[t]; sW5[t] = W5[t];
                   sW6[t] = W6[t]; sW7[t] = W7[t]; sW8[t] = W8[t]; }
    if (t < 69) sb0[t] = b0[t];
    if (t < 31) sb1[t] = b1[t];
    if (t < 10) { sb2[t] = b2[t]; sb3[t] = b3[t]; sb4[t] = b4[t];
                  sb5[t] = b5[t]; sb6[t] = b6[t]; sb7[t] = b7[t];
                  sb8[t] = b8[t]; }
    __syncthreads();

    if (t < 100) A[t] = sW8[t];
    if (t < N_OUT) beff[t] = sb8[t];
    __syncthreads();

    fold_step<10, 10>(A, T, beff, sW7, sb7, t);
    fold_step<10, 10>(A, T, beff, sW6, sb6, t);
    fold_step<10, 10>(A, T, beff, sW5, sb5, t);
    fold_step<10, 10>(A, T, beff, sW4, sb4, t);
    fold_step<10, 10>(A, T, beff, sW3, sb3, t);
    fold_step<10, 31>(A, T, beff, sW2, sb2, t);
    fold_step<31, 69>(A, T, beff, sW1, sb1, t);   // A now [10,69]

    if (blockIdx.x == 0 && t < N_OUT) {
        float s = 0.f;
#pragma unroll
        for (int k = 0; k < 69; ++k) s += A[t * 69 + k] * sb0[k];
        g_beff[t] = beff[t] + s;
    }

    if (t < 112) {
        const int col = blockIdx.x * 112 + t;
        float acc[N_OUT];
#pragma unroll
        for (int r = 0; r < N_OUT; ++r) acc[r] = 0.f;
#pragma unroll
        for (int k = 0; k < 69; ++k) {
            float w0 = W0[k * K_IN + col];
#pragma unroll
            for (int r = 0; r < N_OUT; ++r) acc[r] += A[r * 69 + k] * w0;
        }
#pragma unroll
        for (int r = 0; r < N_OUT; ++r) g_Weff[r * K_IN + col] = acc[r];
    }
}

// ---------------------------------------------------------------------------
// gemv_pipe
// ---------------------------------------------------------------------------
__device__ __forceinline__ void cp16(float* s, const float* g)
{
    unsigned saddr = (unsigned)__cvta_generic_to_shared(s);
    asm volatile("cp.async.cg.shared.global [%0], [%1], 16;\n"
                 :: "r"(saddr), "l"(g));
}

// stage 16 rows x 32 cols into a 512-float buffer (4 LDGSTS per lane)
__device__ __forceinline__ void stage_chunk(
    float* dst, const float* xw, int c0, int rg, int kg)
{
#pragma unroll
    for (int q = 0; q < 4; ++q) {
        const int row = q * 4 + rg;                 // quarter-warp = 4 rows
        cp16(dst + row * 32 + 4 * kg,
             xw + (size_t)row * K_IN + c0 + 4 * kg);
    }
}

__global__ __launch_bounds__(256, 2) void gemv_pipe(
    const float* __restrict__ x, float* __restrict__ y, int B)
{
    extern __shared__ float smem[];
    float* sW   = smem;            // 7840 + pad
    float* sb   = smem + 7856;     // 10 bias (region padded to 7872)
    float* xbuf = smem + 7872;     // 8 warps * DEPTH * STGF floats

    const int tid = threadIdx.x;

    for (int i = tid; i < N_OUT * K_IN; i += 256) sW[i] = g_Weff[i];
    if (tid < 16) sW[N_OUT * K_IN + tid] = 0.f;
    if (tid < N_OUT) sb[tid] = g_beff[tid];
    __syncthreads();

    const int lane = tid & 31;
    const int warp = tid >> 5;
    const int kg = lane & 7;            // column lane (16B granule)
    const int rg = lane >> 3;           // quarter-warp / row group
    int rowbase = blockIdx.x * 128 + warp * 16;
    if (rowbase > B - 16) rowbase = (B >= 16) ? (B - 16) : 0;  // benign dup

    const float* xw = x + (size_t)rowbase * K_IN;
    float* mybuf = xbuf + warp * (DEPTH * STGF);

    // ---- prologue: fill the ring ----
#pragma unroll
    for (int s = 0; s < DEPTH; ++s) {
        stage_chunk(mybuf + s * STGF, xw, 32 * s, rg, kg);
        asm volatile("cp.async.commit_group;\n");
    }

    float acc[N_OUT][4];
#pragma unroll
    for (int j = 0; j < N_OUT; ++j)
#pragma unroll
        for (int r = 0; r < 4; ++r) acc[j][r] = 0.f;

    // ---- mainloop: 24 full 32-col chunks ----
#pragma unroll 1
    for (int i = 0; i < 24; ++i) {
        asm volatile("cp.async.wait_group %0;\n" :: "n"(DEPTH - 1));
        __syncwarp();

        const float* bufp = mybuf + (i & (DEPTH - 1)) * STGF;
        const int c = 4 * kg + 32 * i;

        float4 xv[4];
#pragma unroll
        for (int r = 0; r < 4; ++r)
            xv[r] = *reinterpret_cast<const float4*>(
                bufp + (rg * 4 + r) * 32 + 4 * kg);

#pragma unroll
        for (int j = 0; j < N_OUT; ++j) {
            float4 w = *reinterpret_cast<const float4*>(&sW[j * K_IN + c]);
#pragma unroll
            for (int r = 0; r < 4; ++r) {
                acc[j][r] += xv[r].x * w.x;
                acc[j][r] += xv[r].y * w.y;
                acc[j][r] += xv[r].z * w.z;
                acc[j][r] += xv[r].w * w.w;
            }
        }

        __syncwarp();   // all lanes done reading this buffer
        if (i + DEPTH < 24)
            stage_chunk(mybuf + (i & (DEPTH - 1)) * STGF, xw,
                        32 * (i + DEPTH), rg, kg);
        asm volatile("cp.async.commit_group;\n");   // empty group is legal
    }

    // ---- tail: cols 768..783 directly from global (kg < 4 only) ----
    if (kg < 4) {
        const int c = 768 + 4 * kg;
#pragma unroll
        for (int r = 0; r < 4; ++r) {
            float4 xv = *reinterpret_cast<const float4*>(
                xw + (size_t)(rg * 4 + r) * K_IN + c);
#pragma unroll
            for (int j = 0; j < N_OUT; ++j) {
                float4 w = *reinterpret_cast<const float4*>(&sW[j * K_IN + c]);
                acc[j][r] += xv.x * w.x;
                acc[j][r] += xv.y * w.y;
                acc[j][r] += xv.z * w.z;
                acc[j][r] += xv.w * w.w;
            }
        }
    }

    // ---- butterfly reduce over the 8 kg lanes ----
#pragma unroll
    for (int m = 1; m <= 4; m <<= 1)
#pragma unroll
        for (int j = 0; j < N_OUT; ++j)
#pragma unroll
            for (int r = 0; r < 4; ++r)
                acc[j][r] += __shfl_xor_sync(0xFFFFFFFFu, acc[j][r], m);

    // ---- stores: lanes kg=0..4 write float2 pair #kg for their 4 rows ----
    const int row0 = rowbase + rg * 4;
    if (kg < 5) {
#pragma unroll
        for (int r = 0; r < 4; ++r) {
            const int row = row0 + r;
            if (row < B) {
                float2 v;
                v.x = acc[2 * kg][r]     + sb[2 * kg];
                v.y = acc[2 * kg + 1][r] + sb[2 * kg + 1];
                *reinterpret_cast<float2*>(y + (size_t)row * N_OUT + 2 * kg) = v;
            }
        }
    }
}

// ---------------------------------------------------------------------------
extern "C" void kernel_launch(void* const* d_in, const int* in_sizes, int n_in,
                              void* d_out, int out_size)
{
    const float* x = (const float*)d_in[0];
    const float* W[9];
    const float* b[9];
    for (int i = 0; i < 9; ++i) {
        W[i] = (const float*)d_in[1 + 2 * i];
        b[i] = (const float*)d_in[2 + 2 * i];
    }
    const int B = in_sizes[0] / K_IN;

    fold_fused<<<7, 768>>>(W[0], b[0], W[1], b[1], W[2], b[2], W[3], b[3],
                           W[4], b[4], W[5], b[5], W[6], b[6], W[7], b[7],
                           W[8], b[8]);

    const int smem_bytes = (7872 + 8 * DEPTH * STGF) * sizeof(float);  // ~97KB
    static bool attr_set = false;
    if (!attr_set) {
        cudaFuncSetAttribute(gemv_pipe,
                             cudaFuncAttributeMaxDynamicSharedMemorySize,
                             smem_bytes);
        attr_set = true;
    }

    float* y = (float*)d_out;
    gemv_pipe<<<(B + 127) / 128, 256, smem_bytes>>>(x, y, B);
}